// round 11
// baseline (speedup 1.0000x reference)
#include <cuda_runtime.h>
#include <cuda_bf16.h>

#define N_NODES    100000
#define OUTPUT_DIM 128
#define MAX_NNZ    2000000
#define KEEP_INV   (1.0f / 0.9f)

// Static device scratch (no allocations allowed)
__device__ int    g_row_start[N_NODES + 1]; // CSR row pointers
__device__ float2 g_packed[MAX_NNZ];        // (v*KEEP_INV or 0, col-as-float-bits)

__device__ __forceinline__ void fill_rowptr(int rprev, int r, int i) {
    for (int x = rprev + 1; x <= r; ++x) g_row_start[x] = i;
}

// ---------------------------------------------------------------------------
// Kernel 1 (fused prologue, x4 vectorized): for each nnz i
//   - CSR rowptr fill from sorted rows
//   - dropout applied: packed[i] = (keep ? v/keep_prob : 0, colbits)
// Mask dtype detected PER BLOCK from the same 256-element window (identical
// answer in every block -> deterministic, no serialized detect kernel).
//   keep_prob = 0.9 =>
//     uint8 layout  -> ~90% of first 256 bytes equal 0x01
//     int32 layout  -> bytes==1 only ~22%
//     float32 layout-> bytes==1 ~0%
// ---------------------------------------------------------------------------
__global__ void __launch_bounds__(256)
pack_and_rowptr_kernel(const float* __restrict__ values,
                       const int*   __restrict__ rows,
                       const int*   __restrict__ cols,
                       const unsigned char* __restrict__ m,
                       int nnz)
{
    // ---- per-block mask dtype detect (identical in every block) ----
    __shared__ int s_cnt[2][8];
    __shared__ int s_mode;
    {
        const int tid = threadIdx.x;
        const int n   = nnz < 256 ? nnz : 256;
        const int* mi = (const int*)m;

        int u8 = 0, i32 = 0;
        if (tid < n) {
            if (m[tid]  == 1) u8++;
            if (mi[tid] == 1) i32++;
        }
        #pragma unroll
        for (int off = 16; off > 0; off >>= 1) {
            u8  += __shfl_down_sync(0xffffffffu, u8,  off);
            i32 += __shfl_down_sync(0xffffffffu, i32, off);
        }
        const int wid = tid >> 5, lane = tid & 31;
        if (lane == 0) { s_cnt[0][wid] = u8; s_cnt[1][wid] = i32; }
        __syncthreads();
        if (tid == 0) {
            int tu8 = 0, ti32 = 0;
            #pragma unroll
            for (int w = 0; w < 8; ++w) { tu8 += s_cnt[0][w]; ti32 += s_cnt[1][w]; }
            int mode;
            if (tu8 * 4 > n * 3)       mode = 0;     // byte mask
            else if (ti32 * 4 > n * 3) mode = 1;     // int32 mask
            else                       mode = 2;     // float32 mask
            s_mode = mode;
        }
        __syncthreads();
    }
    const int mode = s_mode;

    const int base = (blockIdx.x * blockDim.x + threadIdx.x) * 4;
    if (base >= nnz) return;

    if (base + 4 <= nnz) {
        // ---- fast vectorized path ----
        const int4   r4 = *(const int4*)(rows + base);
        const float4 v4 = *(const float4*)(values + base);
        const int4   c4 = *(const int4*)(cols + base);

        // CSR rowptr for the 4 consecutive entries
        const int rprev = (base == 0) ? -1 : rows[base - 1];
        fill_rowptr(rprev, r4.x, base + 0);
        fill_rowptr(r4.x,  r4.y, base + 1);
        fill_rowptr(r4.y,  r4.z, base + 2);
        fill_rowptr(r4.z,  r4.w, base + 3);
        if (base + 4 == nnz) fill_rowptr(r4.w, N_NODES, nnz);

        // dropout keep flags (dtype per detected mode)
        bool k0, k1, k2, k3;
        if (mode == 0) {
            const uchar4 mm = *(const uchar4*)(m + base);
            k0 = mm.x != 0; k1 = mm.y != 0; k2 = mm.z != 0; k3 = mm.w != 0;
        } else if (mode == 1) {
            const int4 mm = *(const int4*)((const int*)m + base);
            k0 = mm.x != 0; k1 = mm.y != 0; k2 = mm.z != 0; k3 = mm.w != 0;
        } else {
            const float4 mm = *(const float4*)((const float*)m + base);
            k0 = mm.x != 0.0f; k1 = mm.y != 0.0f; k2 = mm.z != 0.0f; k3 = mm.w != 0.0f;
        }

        float4 p01, p23;   // two packed float2 pairs
        p01.x = k0 ? v4.x * KEEP_INV : 0.0f;  p01.y = __int_as_float(c4.x);
        p01.z = k1 ? v4.y * KEEP_INV : 0.0f;  p01.w = __int_as_float(c4.y);
        p23.x = k2 ? v4.z * KEEP_INV : 0.0f;  p23.y = __int_as_float(c4.z);
        p23.z = k3 ? v4.w * KEEP_INV : 0.0f;  p23.w = __int_as_float(c4.w);
        float4* dst = (float4*)(g_packed + base);  // base%4==0 -> 32B aligned
        dst[0] = p01;
        dst[1] = p23;
    } else {
        // ---- scalar tail ----
        for (int i = base; i < nnz; ++i) {
            const int r = rows[i];
            const int rprev = (i == 0) ? -1 : rows[i - 1];
            fill_rowptr(rprev, r, i);
            if (i == nnz - 1) fill_rowptr(r, N_NODES, nnz);

            bool keep;
            if (mode == 0)      keep = m[i] != 0;
            else if (mode == 1) keep = ((const int*)m)[i] != 0;
            else                keep = ((const float*)m)[i] != 0.0f;
            const float v = keep ? values[i] * KEEP_INV : 0.0f;
            g_packed[i] = make_float2(v, __int_as_float(cols[i]));
        }
    }
}

// ---------------------------------------------------------------------------
// Kernel 2: one warp per output row, lane l owns output columns [4l, 4l+4).
// Per nnz: one warp-uniform LDG.64 of (v, colbits), then an UNCONDITIONAL
// coalesced 512B W-row gather and FMA. Dropped entries carry v=0, so the
// unguarded FMA adds exactly zero — and with no branch between the packed
// load and the gather, the addresses of successive iterations are fully
// independent: ptxas front-batches 4 gathers per unrolled group, quartering
// the exposed L2 latency that bound R9 (~450 cyc/nnz serial).
// Exclusive row ownership -> plain float4 store, bias fused, no atomics.
// ---------------------------------------------------------------------------
__global__ void __launch_bounds__(256)
spmm_warp_per_row_kernel(const float4* __restrict__ W4,     // [INPUT_DIM][32] float4
                         const float4* __restrict__ bias4,  // [32] float4
                         float4* __restrict__ out4)         // [N_NODES][32] float4
{
    const int warp = (blockIdx.x * blockDim.x + threadIdx.x) >> 5;
    const int lane = threadIdx.x & 31;
    if (warp >= N_NODES) return;

    const int s = g_row_start[warp];
    const int e = g_row_start[warp + 1];

    float4 acc = bias4[lane];

    #pragma unroll 4
    for (int k = s; k < e; ++k) {
        const float2 p = g_packed[k];                // warp-uniform broadcast
        const float4 w = W4[__float_as_int(p.y) * 32 + lane];  // unconditional
        acc.x += p.x * w.x;
        acc.y += p.x * w.y;
        acc.z += p.x * w.z;
        acc.w += p.x * w.w;
    }

    out4[warp * 32 + lane] = acc;                    // 512B coalesced per warp
}

// ---------------------------------------------------------------------------
// kernel_launch — inputs per setup_inputs() order:
//   0: values  float32 [NNZ]
//   1: rows    int32   [NNZ] (sorted)
//   2: cols    int32   [NNZ]
//   3: keep_mask (bool-ish, dtype auto-detected)
//   4: weights float32 [INPUT_DIM, 128]
//   5: bias    float32 [128]
// ---------------------------------------------------------------------------
extern "C" void kernel_launch(void* const* d_in, const int* in_sizes, int n_in,
                              void* d_out, int out_size)
{
    const float* values = (const float*)d_in[0];
    const int*   rows   = (const int*)  d_in[1];
    const int*   cols   = (const int*)  d_in[2];
    const void*  mask   =               d_in[3];
    const float4* W4    = (const float4*)d_in[4];
    const float4* bias4 = (const float4*)d_in[5];
    float4* out4        = (float4*)d_out;

    const int nnz = in_sizes[0];

    {
        const int threads = 256;
        const int elems_per_block = threads * 4;
        const int blocks = (nnz + elems_per_block - 1) / elems_per_block;
        pack_and_rowptr_kernel<<<blocks, threads>>>(
            values, rows, cols, (const unsigned char*)mask, nnz);
    }

    {
        const int warps_per_block = 8;                 // 256 threads
        const int blocks = (N_NODES + warps_per_block - 1) / warps_per_block;
        spmm_warp_per_row_kernel<<<blocks, 256>>>(W4, bias4, out4);
    }
}

// round 12
// speedup vs baseline: 1.3715x; 1.3715x over previous
#include <cuda_runtime.h>
#include <cuda_bf16.h>

#define N_NODES    100000
#define OUTPUT_DIM 128
#define MAX_NNZ    2000000
#define KEEP_INV   (1.0f / 0.9f)

// Static device scratch (no allocations allowed)
__device__ int    g_row_start[N_NODES + 1]; // CSR row pointers
__device__ float2 g_packed[MAX_NNZ];        // (v*KEEP_INV or 0, col-as-float-bits)

__device__ __forceinline__ void fill_rowptr(int rprev, int r, int i) {
    for (int x = rprev + 1; x <= r; ++x) g_row_start[x] = i;
}

// ---------------------------------------------------------------------------
// Kernel 1 (fused prologue, x4 vectorized — unchanged from R11, measured
// ~12.9us): per nnz i build CSR rowptr from sorted rows and pack
// (keep ? v/keep_prob : 0, colbits). Mask dtype detected per block from the
// same 256-element window (identical answer in every block -> deterministic).
// ---------------------------------------------------------------------------
__global__ void __launch_bounds__(256)
pack_and_rowptr_kernel(const float* __restrict__ values,
                       const int*   __restrict__ rows,
                       const int*   __restrict__ cols,
                       const unsigned char* __restrict__ m,
                       int nnz)
{
    // ---- per-block mask dtype detect (identical in every block) ----
    __shared__ int s_cnt[2][8];
    __shared__ int s_mode;
    {
        const int tid = threadIdx.x;
        const int n   = nnz < 256 ? nnz : 256;
        const int* mi = (const int*)m;

        int u8 = 0, i32 = 0;
        if (tid < n) {
            if (m[tid]  == 1) u8++;
            if (mi[tid] == 1) i32++;
        }
        #pragma unroll
        for (int off = 16; off > 0; off >>= 1) {
            u8  += __shfl_down_sync(0xffffffffu, u8,  off);
            i32 += __shfl_down_sync(0xffffffffu, i32, off);
        }
        const int wid = tid >> 5, lane = tid & 31;
        if (lane == 0) { s_cnt[0][wid] = u8; s_cnt[1][wid] = i32; }
        __syncthreads();
        if (tid == 0) {
            int tu8 = 0, ti32 = 0;
            #pragma unroll
            for (int w = 0; w < 8; ++w) { tu8 += s_cnt[0][w]; ti32 += s_cnt[1][w]; }
            int mode;
            if (tu8 * 4 > n * 3)       mode = 0;     // byte mask
            else if (ti32 * 4 > n * 3) mode = 1;     // int32 mask
            else                       mode = 2;     // float32 mask
            s_mode = mode;
        }
        __syncthreads();
    }
    const int mode = s_mode;

    const int base = (blockIdx.x * blockDim.x + threadIdx.x) * 4;
    if (base >= nnz) return;

    if (base + 4 <= nnz) {
        const int4   r4 = *(const int4*)(rows + base);
        const float4 v4 = *(const float4*)(values + base);
        const int4   c4 = *(const int4*)(cols + base);

        const int rprev = (base == 0) ? -1 : rows[base - 1];
        fill_rowptr(rprev, r4.x, base + 0);
        fill_rowptr(r4.x,  r4.y, base + 1);
        fill_rowptr(r4.y,  r4.z, base + 2);
        fill_rowptr(r4.z,  r4.w, base + 3);
        if (base + 4 == nnz) fill_rowptr(r4.w, N_NODES, nnz);

        bool k0, k1, k2, k3;
        if (mode == 0) {
            const uchar4 mm = *(const uchar4*)(m + base);
            k0 = mm.x != 0; k1 = mm.y != 0; k2 = mm.z != 0; k3 = mm.w != 0;
        } else if (mode == 1) {
            const int4 mm = *(const int4*)((const int*)m + base);
            k0 = mm.x != 0; k1 = mm.y != 0; k2 = mm.z != 0; k3 = mm.w != 0;
        } else {
            const float4 mm = *(const float4*)((const float*)m + base);
            k0 = mm.x != 0.0f; k1 = mm.y != 0.0f; k2 = mm.z != 0.0f; k3 = mm.w != 0.0f;
        }

        float4 p01, p23;
        p01.x = k0 ? v4.x * KEEP_INV : 0.0f;  p01.y = __int_as_float(c4.x);
        p01.z = k1 ? v4.y * KEEP_INV : 0.0f;  p01.w = __int_as_float(c4.y);
        p23.x = k2 ? v4.z * KEEP_INV : 0.0f;  p23.y = __int_as_float(c4.z);
        p23.z = k3 ? v4.w * KEEP_INV : 0.0f;  p23.w = __int_as_float(c4.w);
        float4* dst = (float4*)(g_packed + base);
        dst[0] = p01;
        dst[1] = p23;
    } else {
        for (int i = base; i < nnz; ++i) {
            const int r = rows[i];
            const int rprev = (i == 0) ? -1 : rows[i - 1];
            fill_rowptr(rprev, r, i);
            if (i == nnz - 1) fill_rowptr(r, N_NODES, nnz);

            bool keep;
            if (mode == 0)      keep = m[i] != 0;
            else if (mode == 1) keep = ((const int*)m)[i] != 0;
            else                keep = ((const float*)m)[i] != 0.0f;
            const float v = keep ? values[i] * KEEP_INV : 0.0f;
            g_packed[i] = make_float2(v, __int_as_float(cols[i]));
        }
    }
}

// ---------------------------------------------------------------------------
// Kernel 2: one warp per output row, lane l owns output columns [4l, 4l+4).
//
// EXPLICIT 4-deep gather batching with an adequate register budget:
//   - 4 warp-uniform LDG.64 packed loads (independent)
//   - 4 unconditional, independent 512B W-row gathers (LDG.128)
//   - 16 FFMAs
// Dropped entries carry v=0, so unguarded FMAs are exact. No shfl, no
// predicated selects, no branch between load and gather.
// __launch_bounds__(256, 5) -> 51-reg ceiling: the ~44-reg body fits with
// NO SPILLS (the R11 regression: ptxas pinned 32 regs and spilled the
// batched W values through local memory). Occupancy ~40 warps/SM is ample
// cover once each warp has 4 gathers in flight.
// Exclusive row ownership -> plain float4 store, bias fused, no atomics.
// ---------------------------------------------------------------------------
__global__ void __launch_bounds__(256, 5)
spmm_warp_per_row_kernel(const float4* __restrict__ W4,     // [INPUT_DIM][32] float4
                         const float4* __restrict__ bias4,  // [32] float4
                         float4* __restrict__ out4)         // [N_NODES][32] float4
{
    const int warp = (blockIdx.x * blockDim.x + threadIdx.x) >> 5;
    const int lane = threadIdx.x & 31;
    if (warp >= N_NODES) return;

    const int s = g_row_start[warp];
    const int e = g_row_start[warp + 1];

    float4 acc = bias4[lane];

    int k = s;
    for (; k + 4 <= e; k += 4) {
        // 4 independent warp-uniform packed loads
        const float2 p0 = g_packed[k + 0];
        const float2 p1 = g_packed[k + 1];
        const float2 p2 = g_packed[k + 2];
        const float2 p3 = g_packed[k + 3];
        // 4 independent unconditional gathers — all in flight together
        const float4 w0 = W4[__float_as_int(p0.y) * 32 + lane];
        const float4 w1 = W4[__float_as_int(p1.y) * 32 + lane];
        const float4 w2 = W4[__float_as_int(p2.y) * 32 + lane];
        const float4 w3 = W4[__float_as_int(p3.y) * 32 + lane];

        acc.x += p0.x * w0.x; acc.y += p0.x * w0.y; acc.z += p0.x * w0.z; acc.w += p0.x * w0.w;
        acc.x += p1.x * w1.x; acc.y += p1.x * w1.y; acc.z += p1.x * w1.z; acc.w += p1.x * w1.w;
        acc.x += p2.x * w2.x; acc.y += p2.x * w2.y; acc.z += p2.x * w2.z; acc.w += p2.x * w2.w;
        acc.x += p3.x * w3.x; acc.y += p3.x * w3.y; acc.z += p3.x * w3.z; acc.w += p3.x * w3.w;
    }
    #pragma unroll 1
    for (; k < e; ++k) {
        const float2 p = g_packed[k];
        const float4 w = W4[__float_as_int(p.y) * 32 + lane];
        acc.x += p.x * w.x;
        acc.y += p.x * w.y;
        acc.z += p.x * w.z;
        acc.w += p.x * w.w;
    }

    out4[warp * 32 + lane] = acc;                    // 512B coalesced per warp
}

// ---------------------------------------------------------------------------
// kernel_launch — inputs per setup_inputs() order:
//   0: values  float32 [NNZ]
//   1: rows    int32   [NNZ] (sorted)
//   2: cols    int32   [NNZ]
//   3: keep_mask (bool-ish, dtype auto-detected)
//   4: weights float32 [INPUT_DIM, 128]
//   5: bias    float32 [128]
// ---------------------------------------------------------------------------
extern "C" void kernel_launch(void* const* d_in, const int* in_sizes, int n_in,
                              void* d_out, int out_size)
{
    const float* values = (const float*)d_in[0];
    const int*   rows   = (const int*)  d_in[1];
    const int*   cols   = (const int*)  d_in[2];
    const void*  mask   =               d_in[3];
    const float4* W4    = (const float4*)d_in[4];
    const float4* bias4 = (const float4*)d_in[5];
    float4* out4        = (float4*)d_out;

    const int nnz = in_sizes[0];

    {
        const int threads = 256;
        const int elems_per_block = threads * 4;
        const int blocks = (nnz + elems_per_block - 1) / elems_per_block;
        pack_and_rowptr_kernel<<<blocks, threads>>>(
            values, rows, cols, (const unsigned char*)mask, nnz);
    }

    {
        const int warps_per_block = 8;                 // 256 threads
        const int blocks = (N_NODES + warps_per_block - 1) / warps_per_block;
        spmm_warp_per_row_kernel<<<blocks, 256>>>(W4, bias4, out4);
    }
}